// round 8
// baseline (speedup 1.0000x reference)
#include <cuda_runtime.h>
#include <math.h>

#define MAXN 100000
#define MAXE 1600000
#define MAXT (MAXN + MAXE)
#define NB_MAX 1024

// ---------------- static device scratch -------------------------------------
__device__ __align__(16) float g_h1  [MAXN * 64];
__device__ __align__(16) float g_as1 [MAXN * 4];
__device__ __align__(16) float g_ad1 [MAXN * 4];
__device__ __align__(16) float g_h2  [MAXN * 40];
__device__            float g_as2 [MAXN];
__device__            float g_ad2 [MAXN];
// CSR structures (rebuilt every launch; dst-sorted). Padded so int4/scan code
// never needs bounds checks.
__device__ int g_deg     [MAXN + 1024];
__device__ int g_rowstart[MAXN + 1024];
__device__ int g_cursor  [MAXN + 1024];
__device__ int g_srcs    [MAXT];
__device__ int g_bsum[NB_MAX];
__device__ int g_boff[NB_MAX];

__device__ __forceinline__ float lrelu(float v) { return v > 0.f ? v : 0.2f * v; }

// ---------------- CSR build --------------------------------------------------
__global__ void k_zero_deg(int n) {
    int i = blockIdx.x * blockDim.x + threadIdx.x;
    if (i < n) g_deg[i] = 0;
}

__global__ void k_hist(const int* __restrict__ ei, int e, int n) {
    int t = blockIdx.x * blockDim.x + threadIdx.x;
    if (t >= e + n) return;
    int dst = (t < e) ? __ldg(&ei[e + t]) : (t - e);
    atomicAdd(&g_deg[dst], 1);
}

__global__ void k_blocksum() {
    __shared__ int wsum[8];
    int b = blockIdx.x, tid = threadIdx.x;
    int4 d = *(const int4*)&g_deg[b * 1024 + tid * 4];
    int s = d.x + d.y + d.z + d.w;
    #pragma unroll
    for (int off = 16; off; off >>= 1) s += __shfl_down_sync(0xffffffffu, s, off);
    if ((tid & 31) == 0) wsum[tid >> 5] = s;
    __syncthreads();
    if (tid == 0) {
        int t = 0;
        #pragma unroll
        for (int i = 0; i < 8; i++) t += wsum[i];
        g_bsum[b] = t;
    }
}

__global__ void k_scanb(int nb, int n) {
    __shared__ int sm[1024];
    int tid = threadIdx.x;
    int v = (tid < nb) ? g_bsum[tid] : 0;
    sm[tid] = v;
    __syncthreads();
    for (int off = 1; off < 1024; off <<= 1) {
        int a = (tid >= off) ? sm[tid - off] : 0;
        __syncthreads();
        sm[tid] += a;
        __syncthreads();
    }
    if (tid < nb) g_boff[tid] = sm[tid] - v;
    if (tid == 1023) g_rowstart[n] = sm[1023];
}

__global__ void k_writerow() {
    __shared__ int tsum[256];
    int b = blockIdx.x, tid = threadIdx.x;
    int idx = b * 1024 + tid * 4;
    int4 d = *(const int4*)&g_deg[idx];
    int s = d.x + d.y + d.z + d.w;
    tsum[tid] = s;
    __syncthreads();
    for (int off = 1; off < 256; off <<= 1) {
        int a = (tid >= off) ? tsum[tid - off] : 0;
        __syncthreads();
        tsum[tid] += a;
        __syncthreads();
    }
    int r = tsum[tid] - s + g_boff[b];
    g_rowstart[idx] = r;     g_cursor[idx] = r;     r += d.x;
    g_rowstart[idx + 1] = r; g_cursor[idx + 1] = r; r += d.y;
    g_rowstart[idx + 2] = r; g_cursor[idx + 2] = r; r += d.z;
    g_rowstart[idx + 3] = r; g_cursor[idx + 3] = r;
}

__global__ void k_scatter(const int* __restrict__ ei, int e, int n) {
    int t = blockIdx.x * blockDim.x + threadIdx.x;
    if (t >= e + n) return;
    int src, dst;
    if (t < e) { src = __ldg(&ei[t]); dst = __ldg(&ei[e + t]); } else { src = dst = t - e; }
    int pos = atomicAdd(&g_cursor[dst], 1);
    g_srcs[pos] = src;
}

// ------- tiled GEMM1 + fused alpha1 ------------------------------------------
#define G1_TM 64
__global__ void k_gemm1(const float* __restrict__ x, const float* __restrict__ W1,
                        const float* __restrict__ a_s, const float* __restrict__ a_d,
                        int n) {
    __shared__ float As[G1_TM * 68];
    __shared__ float Bs[64 * 64];
    int tid = threadIdx.x;
    int row0 = blockIdx.x * G1_TM;
    int tr = tid >> 4, tc = tid & 15;

    float acc[4][4] = {};
    const float4* Bs4 = (const float4*)Bs;

    #pragma unroll
    for (int kt = 0; kt < 2; kt++) {
        for (int i = tid; i < 64 * 64; i += 256) {
            int c = i >> 6, kk = i & 63;
            Bs[kk * 64 + c] = W1[c * 128 + kt * 64 + kk];
        }
        for (int i = tid; i < G1_TM * 16; i += 256) {
            int r = i >> 4, k4 = i & 15;
            int row = row0 + r;
            float4 v = (row < n) ? *(const float4*)&x[(size_t)row * 128 + kt * 64 + k4 * 4]
                                 : make_float4(0.f, 0.f, 0.f, 0.f);
            *(float4*)&As[r * 68 + k4 * 4] = v;
        }
        __syncthreads();

        #pragma unroll 4
        for (int k = 0; k < 64; k++) {
            float a0 = As[(tr * 4 + 0) * 68 + k];
            float a1 = As[(tr * 4 + 1) * 68 + k];
            float a2 = As[(tr * 4 + 2) * 68 + k];
            float a3 = As[(tr * 4 + 3) * 68 + k];
            float4 b = Bs4[k * 16 + tc];
            acc[0][0] = fmaf(a0, b.x, acc[0][0]); acc[0][1] = fmaf(a0, b.y, acc[0][1]);
            acc[0][2] = fmaf(a0, b.z, acc[0][2]); acc[0][3] = fmaf(a0, b.w, acc[0][3]);
            acc[1][0] = fmaf(a1, b.x, acc[1][0]); acc[1][1] = fmaf(a1, b.y, acc[1][1]);
            acc[1][2] = fmaf(a1, b.z, acc[1][2]); acc[1][3] = fmaf(a1, b.w, acc[1][3]);
            acc[2][0] = fmaf(a2, b.x, acc[2][0]); acc[2][1] = fmaf(a2, b.y, acc[2][1]);
            acc[2][2] = fmaf(a2, b.z, acc[2][2]); acc[2][3] = fmaf(a2, b.w, acc[2][3]);
            acc[3][0] = fmaf(a3, b.x, acc[3][0]); acc[3][1] = fmaf(a3, b.y, acc[3][1]);
            acc[3][2] = fmaf(a3, b.z, acc[3][2]); acc[3][3] = fmaf(a3, b.w, acc[3][3]);
        }
        __syncthreads();
    }

    int col = tc * 4;
    #pragma unroll
    for (int i = 0; i < 4; i++) {
        int row = row0 + tr * 4 + i;
        if (row < n)
            *(float4*)&g_h1[(size_t)row * 64 + col] =
                make_float4(acc[i][0], acc[i][1], acc[i][2], acc[i][3]);
    }

    float as0 = a_s[col], as1v = a_s[col + 1], as2v = a_s[col + 2], as3 = a_s[col + 3];
    float ad0 = a_d[col], ad1v = a_d[col + 1], ad2v = a_d[col + 2], ad3 = a_d[col + 3];
    float ps[4], pd[4];
    #pragma unroll
    for (int i = 0; i < 4; i++) {
        ps[i] = acc[i][0] * as0 + acc[i][1] * as1v + acc[i][2] * as2v + acc[i][3] * as3;
        pd[i] = acc[i][0] * ad0 + acc[i][1] * ad1v + acc[i][2] * ad2v + acc[i][3] * ad3;
    }
    #pragma unroll
    for (int off = 1; off <= 2; off <<= 1) {
        #pragma unroll
        for (int i = 0; i < 4; i++) {
            ps[i] += __shfl_xor_sync(0xffffffffu, ps[i], off);
            pd[i] += __shfl_xor_sync(0xffffffffu, pd[i], off);
        }
    }
    if ((tc & 3) == 0) {
        int head = tc >> 2;
        #pragma unroll
        for (int i = 0; i < 4; i++) {
            int row = row0 + tr * 4 + i;
            if (row < n) {
                g_as1[row * 4 + head] = ps[i];
                g_ad1[row * 4 + head] = pd[i];
            }
        }
    }
}

// ------ layer1 fused: softmax-aggregate + relu+bias + gemm2 + alpha2 ---------
// Half-warp edge pairing: lane li owns channels 4li..4li+3; half h does edges
// k2 = h, h+2, ...; cross-half merge via shfl_xor(16).
__global__ void k_agg1f(const float* __restrict__ b1, const float* __restrict__ W2,
                        const float* __restrict__ a_s2, const float* __restrict__ a_d2,
                        int n) {
    __shared__ float Wt[64 * 40];
    __shared__ float sa[40], sd[40];
    __shared__ __align__(16) float b1s[64];
    __shared__ __align__(16) float es[8][128];
    __shared__ int ss[8][32];
    int tid = threadIdx.x;
    for (int i = tid; i < 40 * 64; i += 256) {
        int c = i / 64, k = i - c * 64;
        Wt[k * 40 + c] = W2[i];
    }
    if (tid < 40) { sa[tid] = a_s2[tid]; sd[tid] = a_d2[tid]; }
    if (tid < 64) b1s[tid] = b1[tid];
    __syncthreads();

    int w = tid >> 5, lane = tid & 31;
    int half = lane >> 4, li = lane & 15;
    int head_g = li >> 2;
    int ngroups = gridDim.x * 8;

    for (int dst = blockIdx.x * 8 + w; dst < n; dst += ngroups) {
        int row = g_rowstart[dst], end = g_rowstart[dst + 1];
        float4 ad = *(const float4*)&g_ad1[dst * 4];
        float4 acc4 = make_float4(0.f, 0.f, 0.f, 0.f);
        float4 den  = make_float4(0.f, 0.f, 0.f, 0.f);

        for (int base = row; base < end; base += 32) {
            int k = base + lane;
            float4 e4 = make_float4(0.f, 0.f, 0.f, 0.f);
            int s = 0;
            if (k < end) {
                s = g_srcs[k];
                float4 as = *(const float4*)&g_as1[s * 4];
                e4.x = __expf(lrelu(as.x + ad.x));
                e4.y = __expf(lrelu(as.y + ad.y));
                e4.z = __expf(lrelu(as.z + ad.z));
                e4.w = __expf(lrelu(as.w + ad.w));
                den.x += e4.x; den.y += e4.y; den.z += e4.z; den.w += e4.w;
            }
            ss[w][lane] = s;
            *(float4*)&es[w][lane * 4] = e4;
            __syncwarp();
            int m = min(32, end - base);
            #pragma unroll 2
            for (int k2 = half; k2 < m; k2 += 2) {
                int s2   = ss[w][k2];
                float ek = es[w][k2 * 4 + head_g];
                float4 h = *(const float4*)&g_h1[(size_t)s2 * 64 + li * 4];
                acc4.x = fmaf(ek, h.x, acc4.x);
                acc4.y = fmaf(ek, h.y, acc4.y);
                acc4.z = fmaf(ek, h.z, acc4.z);
                acc4.w = fmaf(ek, h.w, acc4.w);
            }
            __syncwarp();
        }
        // cross-half merge of channel partials (both halves end with the total)
        acc4.x += __shfl_xor_sync(0xffffffffu, acc4.x, 16);
        acc4.y += __shfl_xor_sync(0xffffffffu, acc4.y, 16);
        acc4.z += __shfl_xor_sync(0xffffffffu, acc4.z, 16);
        acc4.w += __shfl_xor_sync(0xffffffffu, acc4.w, 16);
        // den: full warp reduce
        #pragma unroll
        for (int off = 16; off; off >>= 1) {
            den.x += __shfl_xor_sync(0xffffffffu, den.x, off);
            den.y += __shfl_xor_sync(0xffffffffu, den.y, off);
            den.z += __shfl_xor_sync(0xffffffffu, den.z, off);
            den.w += __shfl_xor_sync(0xffffffffu, den.w, off);
        }
        float d   = head_g == 0 ? den.x : head_g == 1 ? den.y : head_g == 2 ? den.z : den.w;
        float inv = __frcp_rn(d);
        float4 bb = *(const float4*)&b1s[li * 4];
        float4 v;
        v.x = fmaxf(fmaf(acc4.x, inv, bb.x), 0.f);
        v.y = fmaxf(fmaf(acc4.y, inv, bb.y), 0.f);
        v.z = fmaxf(fmaf(acc4.z, inv, bb.z), 0.f);
        v.w = fmaxf(fmaf(acc4.w, inv, bb.w), 0.f);
        // gemm2: o[c] = sum_k v[k]*Wt[k*40+c]; v duplicated across halves
        float o0 = 0.f, o1 = 0.f;
        #pragma unroll
        for (int kk = 0; kk < 16; kk++) {
            float vx = __shfl_sync(0xffffffffu, v.x, kk);
            float vy = __shfl_sync(0xffffffffu, v.y, kk);
            float vz = __shfl_sync(0xffffffffu, v.z, kk);
            float vw = __shfl_sync(0xffffffffu, v.w, kk);
            const float* Wp = &Wt[kk * 4 * 40];
            o0 = fmaf(Wp[lane],       vx, o0);
            o0 = fmaf(Wp[40 + lane],  vy, o0);
            o0 = fmaf(Wp[80 + lane],  vz, o0);
            o0 = fmaf(Wp[120 + lane], vw, o0);
            if (lane < 8) {
                o1 = fmaf(Wp[32 + lane],  vx, o1);
                o1 = fmaf(Wp[72 + lane],  vy, o1);
                o1 = fmaf(Wp[112 + lane], vz, o1);
                o1 = fmaf(Wp[152 + lane], vw, o1);
            }
        }
        g_h2[(size_t)dst * 40 + lane] = o0;
        if (lane < 8) g_h2[(size_t)dst * 40 + 32 + lane] = o1;
        float ps = o0 * sa[lane] + (lane < 8 ? o1 * sa[32 + lane] : 0.f);
        float pd = o0 * sd[lane] + (lane < 8 ? o1 * sd[32 + lane] : 0.f);
        #pragma unroll
        for (int off = 16; off; off >>= 1) {
            ps += __shfl_xor_sync(0xffffffffu, ps, off);
            pd += __shfl_xor_sync(0xffffffffu, pd, off);
        }
        if (lane == 0) { g_as2[dst] = ps; g_ad2[dst] = pd; }
    }
}

// ------ layer2 fused: softmax-aggregate + bias + log_softmax -> out ----------
__global__ void k_agg2f(const float* __restrict__ b2, float* __restrict__ out, int n) {
    __shared__ float es[8][32];
    __shared__ int   ss[8][32];
    __shared__ __align__(16) float b2s[48];
    int tid = threadIdx.x;
    if (tid < 40) b2s[tid] = b2[tid];
    if (tid >= 40 && tid < 48) b2s[tid] = 0.f;
    __syncthreads();

    int w = tid >> 5, lane = tid & 31;
    int half = lane >> 4, li = lane & 15;
    bool act = li < 10;
    int ngroups = gridDim.x * 8;
    float4 b24 = act ? *(const float4*)&b2s[li * 4] : make_float4(0.f, 0.f, 0.f, 0.f);

    for (int dst = blockIdx.x * 8 + w; dst < n; dst += ngroups) {
        int row = g_rowstart[dst], end = g_rowstart[dst + 1];
        float ad = g_ad2[dst];
        float4 acc4 = make_float4(0.f, 0.f, 0.f, 0.f);
        float den = 0.f;

        for (int base = row; base < end; base += 32) {
            int k = base + lane;
            float e = 0.f;
            int s = 0;
            if (k < end) {
                s = g_srcs[k];
                e = __expf(lrelu(g_as2[s] + ad));
                den += e;
            }
            ss[w][lane] = s;
            es[w][lane] = e;
            __syncwarp();
            int m = min(32, end - base);
            #pragma unroll 2
            for (int k2 = half; k2 < m; k2 += 2) {
                int s2   = ss[w][k2];
                float ek = es[w][k2];
                if (act) {
                    float4 h = *(const float4*)&g_h2[(size_t)s2 * 40 + li * 4];
                    acc4.x = fmaf(ek, h.x, acc4.x);
                    acc4.y = fmaf(ek, h.y, acc4.y);
                    acc4.z = fmaf(ek, h.z, acc4.z);
                    acc4.w = fmaf(ek, h.w, acc4.w);
                }
            }
            __syncwarp();
        }
        acc4.x += __shfl_xor_sync(0xffffffffu, acc4.x, 16);
        acc4.y += __shfl_xor_sync(0xffffffffu, acc4.y, 16);
        acc4.z += __shfl_xor_sync(0xffffffffu, acc4.z, 16);
        acc4.w += __shfl_xor_sync(0xffffffffu, acc4.w, 16);
        #pragma unroll
        for (int off = 16; off; off >>= 1) den += __shfl_xor_sync(0xffffffffu, den, off);
        float inv = __frcp_rn(den);
        float4 v;
        v.x = fmaf(acc4.x, inv, b24.x);
        v.y = fmaf(acc4.y, inv, b24.y);
        v.z = fmaf(acc4.z, inv, b24.z);
        v.w = fmaf(acc4.w, inv, b24.w);
        // log_softmax over 40 classes (duplicated across halves)
        float mx = act ? fmaxf(fmaxf(v.x, v.y), fmaxf(v.z, v.w)) : -1e30f;
        #pragma unroll
        for (int off = 8; off; off >>= 1) mx = fmaxf(mx, __shfl_xor_sync(0xffffffffu, mx, off));
        float se = act ? (__expf(v.x - mx) + __expf(v.y - mx) + __expf(v.z - mx) + __expf(v.w - mx)) : 0.f;
        #pragma unroll
        for (int off = 8; off; off >>= 1) se += __shfl_xor_sync(0xffffffffu, se, off);
        float ls = mx + logf(se);
        if (half == 0 && act)
            *(float4*)&out[(size_t)dst * 40 + li * 4] =
                make_float4(v.x - ls, v.y - ls, v.z - ls, v.w - ls);
    }
}

// ---------------- launcher ---------------------------------------------------
extern "C" void kernel_launch(void* const* d_in, const int* in_sizes, int n_in,
                              void* d_out, int out_size) {
    const float* x      = (const float*)d_in[0];
    const int*   ei     = (const int*)  d_in[1];
    const float* W1     = (const float*)d_in[2];
    const float* a_src1 = (const float*)d_in[3];
    const float* a_dst1 = (const float*)d_in[4];
    const float* b1     = (const float*)d_in[5];
    const float* W2     = (const float*)d_in[6];
    const float* a_src2 = (const float*)d_in[7];
    const float* a_dst2 = (const float*)d_in[8];
    const float* b2     = (const float*)d_in[9];
    float* out = (float*)d_out;

    int n = in_sizes[0] / 128;
    int e = in_sizes[1] / 2;
    int T = e + n;
    int nb = (n + 1023) >> 10;

    // Fork a second stream for the CSR build (independent of gemm1 chain).
    // Stream/events intentionally NOT destroyed (capture safety; bounded leak).
    cudaStream_t s2;
    cudaStreamCreateWithFlags(&s2, cudaStreamNonBlocking);
    cudaEvent_t evFork, evJoin;
    cudaEventCreateWithFlags(&evFork, cudaEventDisableTiming);
    cudaEventCreateWithFlags(&evJoin, cudaEventDisableTiming);

    cudaEventRecord(evFork, 0);
    cudaStreamWaitEvent(s2, evFork, 0);

    k_zero_deg <<<(n + 255) / 256, 256, 0, s2>>>(n);
    k_hist     <<<(T + 255) / 256, 256, 0, s2>>>(ei, e, n);
    k_blocksum <<<nb, 256, 0, s2>>>();
    k_scanb    <<<1, 1024, 0, s2>>>(nb, n);
    k_writerow <<<nb, 256, 0, s2>>>();
    k_scatter  <<<(T + 255) / 256, 256, 0, s2>>>(ei, e, n);
    cudaEventRecord(evJoin, s2);

    k_gemm1    <<<(n + G1_TM - 1) / G1_TM, 256>>>(x, W1, a_src1, a_dst1, n);

    cudaStreamWaitEvent(0, evJoin, 0);
    k_agg1f    <<<1184, 256>>>(b1, W2, a_src2, a_dst2, n);
    k_agg2f    <<<1184, 256>>>(b2, out, n);
}

// round 10
// speedup vs baseline: 1.0311x; 1.0311x over previous
#include <cuda_runtime.h>
#include <cuda_fp16.h>
#include <math.h>

#define MAXN 100000
#define MAXE 1600000
#define MAXT (MAXN + MAXE)
#define NB_MAX 1024

// ---------------- static device scratch -------------------------------------
__device__ __align__(16) __half g_h1h[MAXN * 64];   // layer1 features, fp16
__device__ __align__(16) float g_as1 [MAXN * 4];
__device__ __align__(16) float g_ad1 [MAXN * 4];
__device__ __align__(16) __half g_h2h[MAXN * 40];   // layer2 features, fp16
__device__            float g_as2 [MAXN];
__device__            float g_ad2 [MAXN];
// CSR structures (rebuilt every launch; dst-sorted). Padded so int4/scan code
// never needs bounds checks.
__device__ int g_deg     [MAXN + 1024];
__device__ int g_rowstart[MAXN + 1024];
__device__ int g_cursor  [MAXN + 1024];
__device__ int g_srcs    [MAXT];
__device__ int g_bsum[NB_MAX];
__device__ int g_boff[NB_MAX];

__device__ __forceinline__ float lrelu(float v) { return v > 0.f ? v : 0.2f * v; }

// ---------------- CSR build --------------------------------------------------
__global__ void k_zero_deg(int n) {
    int i = blockIdx.x * blockDim.x + threadIdx.x;
    if (i < n) g_deg[i] = 0;
}

__global__ void k_hist(const int* __restrict__ ei, int e, int n) {
    int t = blockIdx.x * blockDim.x + threadIdx.x;
    if (t >= e + n) return;
    int dst = (t < e) ? __ldg(&ei[e + t]) : (t - e);
    atomicAdd(&g_deg[dst], 1);
}

__global__ void k_blocksum() {
    __shared__ int wsum[8];
    int b = blockIdx.x, tid = threadIdx.x;
    int4 d = *(const int4*)&g_deg[b * 1024 + tid * 4];
    int s = d.x + d.y + d.z + d.w;
    #pragma unroll
    for (int off = 16; off; off >>= 1) s += __shfl_down_sync(0xffffffffu, s, off);
    if ((tid & 31) == 0) wsum[tid >> 5] = s;
    __syncthreads();
    if (tid == 0) {
        int t = 0;
        #pragma unroll
        for (int i = 0; i < 8; i++) t += wsum[i];
        g_bsum[b] = t;
    }
}

__global__ void k_scanb(int nb, int n) {
    __shared__ int sm[1024];
    int tid = threadIdx.x;
    int v = (tid < nb) ? g_bsum[tid] : 0;
    sm[tid] = v;
    __syncthreads();
    for (int off = 1; off < 1024; off <<= 1) {
        int a = (tid >= off) ? sm[tid - off] : 0;
        __syncthreads();
        sm[tid] += a;
        __syncthreads();
    }
    if (tid < nb) g_boff[tid] = sm[tid] - v;
    if (tid == 1023) g_rowstart[n] = sm[1023];
}

__global__ void k_writerow() {
    __shared__ int tsum[256];
    int b = blockIdx.x, tid = threadIdx.x;
    int idx = b * 1024 + tid * 4;
    int4 d = *(const int4*)&g_deg[idx];
    int s = d.x + d.y + d.z + d.w;
    tsum[tid] = s;
    __syncthreads();
    for (int off = 1; off < 256; off <<= 1) {
        int a = (tid >= off) ? tsum[tid - off] : 0;
        __syncthreads();
        tsum[tid] += a;
        __syncthreads();
    }
    int r = tsum[tid] - s + g_boff[b];
    g_rowstart[idx] = r;     g_cursor[idx] = r;     r += d.x;
    g_rowstart[idx + 1] = r; g_cursor[idx + 1] = r; r += d.y;
    g_rowstart[idx + 2] = r; g_cursor[idx + 2] = r; r += d.z;
    g_rowstart[idx + 3] = r; g_cursor[idx + 3] = r;
}

__global__ void k_scatter(const int* __restrict__ ei, int e, int n) {
    int t = blockIdx.x * blockDim.x + threadIdx.x;
    if (t >= e + n) return;
    int src, dst;
    if (t < e) { src = __ldg(&ei[t]); dst = __ldg(&ei[e + t]); } else { src = dst = t - e; }
    int pos = atomicAdd(&g_cursor[dst], 1);
    g_srcs[pos] = src;
}

// ------- tiled GEMM1 + fused alpha1; h1 stored as fp16 ----------------------
#define G1_TM 64
__global__ void k_gemm1(const float* __restrict__ x, const float* __restrict__ W1,
                        const float* __restrict__ a_s, const float* __restrict__ a_d,
                        int n) {
    __shared__ float As[G1_TM * 68];
    __shared__ float Bs[64 * 64];
    int tid = threadIdx.x;
    int row0 = blockIdx.x * G1_TM;
    int tr = tid >> 4, tc = tid & 15;

    float acc[4][4] = {};
    const float4* Bs4 = (const float4*)Bs;

    #pragma unroll
    for (int kt = 0; kt < 2; kt++) {
        for (int i = tid; i < 64 * 64; i += 256) {
            int c = i >> 6, kk = i & 63;
            Bs[kk * 64 + c] = W1[c * 128 + kt * 64 + kk];
        }
        for (int i = tid; i < G1_TM * 16; i += 256) {
            int r = i >> 4, k4 = i & 15;
            int row = row0 + r;
            float4 v = (row < n) ? *(const float4*)&x[(size_t)row * 128 + kt * 64 + k4 * 4]
                                 : make_float4(0.f, 0.f, 0.f, 0.f);
            *(float4*)&As[r * 68 + k4 * 4] = v;
        }
        __syncthreads();

        #pragma unroll 4
        for (int k = 0; k < 64; k++) {
            float a0 = As[(tr * 4 + 0) * 68 + k];
            float a1 = As[(tr * 4 + 1) * 68 + k];
            float a2 = As[(tr * 4 + 2) * 68 + k];
            float a3 = As[(tr * 4 + 3) * 68 + k];
            float4 b = Bs4[k * 16 + tc];
            acc[0][0] = fmaf(a0, b.x, acc[0][0]); acc[0][1] = fmaf(a0, b.y, acc[0][1]);
            acc[0][2] = fmaf(a0, b.z, acc[0][2]); acc[0][3] = fmaf(a0, b.w, acc[0][3]);
            acc[1][0] = fmaf(a1, b.x, acc[1][0]); acc[1][1] = fmaf(a1, b.y, acc[1][1]);
            acc[1][2] = fmaf(a1, b.z, acc[1][2]); acc[1][3] = fmaf(a1, b.w, acc[1][3]);
            acc[2][0] = fmaf(a2, b.x, acc[2][0]); acc[2][1] = fmaf(a2, b.y, acc[2][1]);
            acc[2][2] = fmaf(a2, b.z, acc[2][2]); acc[2][3] = fmaf(a2, b.w, acc[2][3]);
            acc[3][0] = fmaf(a3, b.x, acc[3][0]); acc[3][1] = fmaf(a3, b.y, acc[3][1]);
            acc[3][2] = fmaf(a3, b.z, acc[3][2]); acc[3][3] = fmaf(a3, b.w, acc[3][3]);
        }
        __syncthreads();
    }

    int col = tc * 4;
    #pragma unroll
    for (int i = 0; i < 4; i++) {
        int row = row0 + tr * 4 + i;
        if (row < n) {
            __half2 p0 = __floats2half2_rn(acc[i][0], acc[i][1]);
            __half2 p1 = __floats2half2_rn(acc[i][2], acc[i][3]);
            *(__half2*)&g_h1h[(size_t)row * 64 + col]     = p0;
            *(__half2*)&g_h1h[(size_t)row * 64 + col + 2] = p1;
        }
    }

    float as0 = a_s[col], as1v = a_s[col + 1], as2v = a_s[col + 2], as3 = a_s[col + 3];
    float ad0 = a_d[col], ad1v = a_d[col + 1], ad2v = a_d[col + 2], ad3 = a_d[col + 3];
    float ps[4], pd[4];
    #pragma unroll
    for (int i = 0; i < 4; i++) {
        ps[i] = acc[i][0] * as0 + acc[i][1] * as1v + acc[i][2] * as2v + acc[i][3] * as3;
        pd[i] = acc[i][0] * ad0 + acc[i][1] * ad1v + acc[i][2] * ad2v + acc[i][3] * ad3;
    }
    #pragma unroll
    for (int off = 1; off <= 2; off <<= 1) {
        #pragma unroll
        for (int i = 0; i < 4; i++) {
            ps[i] += __shfl_xor_sync(0xffffffffu, ps[i], off);
            pd[i] += __shfl_xor_sync(0xffffffffu, pd[i], off);
        }
    }
    if ((tc & 3) == 0) {
        int head = tc >> 2;
        #pragma unroll
        for (int i = 0; i < 4; i++) {
            int row = row0 + tr * 4 + i;
            if (row < n) {
                g_as1[row * 4 + head] = ps[i];
                g_ad1[row * 4 + head] = pd[i];
            }
        }
    }
}

// ------ layer1 fused: softmax-aggregate + relu+bias + gemm2 + alpha2 ---------
// R7 structure (one edge per inner iteration), fp16 h1 gather (half traffic).
__global__ void k_agg1f(const float* __restrict__ b1, const float* __restrict__ W2,
                        const float* __restrict__ a_s2, const float* __restrict__ a_d2,
                        int n) {
    __shared__ float Wt[64 * 40];
    __shared__ float sa[40], sd[40], b1s[64];
    __shared__ __align__(16) float es[8][128];
    __shared__ int ss[8][32];
    int tid = threadIdx.x;
    for (int i = tid; i < 40 * 64; i += 256) {
        int c = i / 64, k = i - c * 64;
        Wt[k * 40 + c] = W2[i];
    }
    if (tid < 40) { sa[tid] = a_s2[tid]; sd[tid] = a_d2[tid]; }
    if (tid < 64) b1s[tid] = b1[tid];
    __syncthreads();

    int w = tid >> 5, lane = tid & 31;
    int head = lane >> 3;
    int ngroups = gridDim.x * 8;

    for (int dst = blockIdx.x * 8 + w; dst < n; dst += ngroups) {
        int row = g_rowstart[dst], end = g_rowstart[dst + 1];
        float4 ad = *(const float4*)&g_ad1[dst * 4];
        float2 acc = make_float2(0.f, 0.f);
        float4 den = make_float4(0.f, 0.f, 0.f, 0.f);

        for (int base = row; base < end; base += 32) {
            int k = base + lane;
            float4 e4 = make_float4(0.f, 0.f, 0.f, 0.f);
            int s = 0;
            if (k < end) {
                s = g_srcs[k];
                float4 as = *(const float4*)&g_as1[s * 4];
                e4.x = __expf(lrelu(as.x + ad.x));
                e4.y = __expf(lrelu(as.y + ad.y));
                e4.z = __expf(lrelu(as.z + ad.z));
                e4.w = __expf(lrelu(as.w + ad.w));
                den.x += e4.x; den.y += e4.y; den.z += e4.z; den.w += e4.w;
            }
            ss[w][lane] = s;
            *(float4*)&es[w][lane * 4] = e4;
            __syncwarp();
            int m = min(32, end - base);
            #pragma unroll 4
            for (int k2 = 0; k2 < m; k2++) {
                int s2   = ss[w][k2];
                float ek = es[w][k2 * 4 + head];
                float2 h = __half22float2(*(const __half2*)&g_h1h[(size_t)s2 * 64 + lane * 2]);
                acc.x = fmaf(ek, h.x, acc.x);
                acc.y = fmaf(ek, h.y, acc.y);
            }
            __syncwarp();
        }
        #pragma unroll
        for (int off = 16; off; off >>= 1) {
            den.x += __shfl_xor_sync(0xffffffffu, den.x, off);
            den.y += __shfl_xor_sync(0xffffffffu, den.y, off);
            den.z += __shfl_xor_sync(0xffffffffu, den.z, off);
            den.w += __shfl_xor_sync(0xffffffffu, den.w, off);
        }
        float d   = head == 0 ? den.x : head == 1 ? den.y : head == 2 ? den.z : den.w;
        float inv = __frcp_rn(d);
        float vx = fmaxf(acc.x * inv + b1s[2 * lane],     0.f);
        float vy = fmaxf(acc.y * inv + b1s[2 * lane + 1], 0.f);
        float o0 = 0.f, o1 = 0.f;
        #pragma unroll
        for (int k = 0; k < 64; k++) {
            float xk = __shfl_sync(0xffffffffu, (k & 1) ? vy : vx, k >> 1);
            o0 = fmaf(Wt[k * 40 + lane], xk, o0);
            if (lane < 8) o1 = fmaf(Wt[k * 40 + 32 + lane], xk, o1);
        }
        g_h2h[(size_t)dst * 40 + lane] = __float2half_rn(o0);
        if (lane < 8) g_h2h[(size_t)dst * 40 + 32 + lane] = __float2half_rn(o1);
        float ps = o0 * sa[lane] + (lane < 8 ? o1 * sa[32 + lane] : 0.f);
        float pd = o0 * sd[lane] + (lane < 8 ? o1 * sd[32 + lane] : 0.f);
        #pragma unroll
        for (int off = 16; off; off >>= 1) {
            ps += __shfl_xor_sync(0xffffffffu, ps, off);
            pd += __shfl_xor_sync(0xffffffffu, pd, off);
        }
        if (lane == 0) { g_as2[dst] = ps; g_ad2[dst] = pd; }
    }
}

// ------ layer2 fused: softmax-aggregate + bias + log_softmax -> out ----------
// Lane li<20 owns channel pair (2li, 2li+1) via half2 gathers.
__global__ void k_agg2f(const float* __restrict__ b2, float* __restrict__ out, int n) {
    __shared__ float es[8][32];
    __shared__ int   ss[8][32];
    int tid = threadIdx.x;
    int w = tid >> 5, lane = tid & 31;
    bool act = lane < 20;
    int ngroups = gridDim.x * 8;

    float b2x = act ? __ldg(&b2[2 * lane])     : 0.f;
    float b2y = act ? __ldg(&b2[2 * lane + 1]) : 0.f;

    for (int dst = blockIdx.x * 8 + w; dst < n; dst += ngroups) {
        int row = g_rowstart[dst], end = g_rowstart[dst + 1];
        float ad = g_ad2[dst];
        float2 acc = make_float2(0.f, 0.f);
        float den = 0.f;

        for (int base = row; base < end; base += 32) {
            int k = base + lane;
            float e = 0.f;
            int s = 0;
            if (k < end) {
                s = g_srcs[k];
                e = __expf(lrelu(g_as2[s] + ad));
                den += e;
            }
            ss[w][lane] = s;
            es[w][lane] = e;
            __syncwarp();
            int m = min(32, end - base);
            #pragma unroll 4
            for (int k2 = 0; k2 < m; k2++) {
                int s2   = ss[w][k2];
                float ek = es[w][k2];
                if (act) {
                    float2 h = __half22float2(*(const __half2*)&g_h2h[(size_t)s2 * 40 + lane * 2]);
                    acc.x = fmaf(ek, h.x, acc.x);
                    acc.y = fmaf(ek, h.y, acc.y);
                }
            }
            __syncwarp();
        }
        #pragma unroll
        for (int off = 16; off; off >>= 1) den += __shfl_xor_sync(0xffffffffu, den, off);
        float inv = __frcp_rn(den);
        float v0 = fmaf(acc.x, inv, b2x);
        float v1 = fmaf(acc.y, inv, b2y);
        float mx = act ? fmaxf(v0, v1) : -1e30f;
        #pragma unroll
        for (int off = 16; off; off >>= 1) mx = fmaxf(mx, __shfl_xor_sync(0xffffffffu, mx, off));
        float se = act ? (__expf(v0 - mx) + __expf(v1 - mx)) : 0.f;
        #pragma unroll
        for (int off = 16; off; off >>= 1) se += __shfl_xor_sync(0xffffffffu, se, off);
        float ls = mx + logf(se);
        if (act)
            *(float2*)&out[(size_t)dst * 40 + lane * 2] = make_float2(v0 - ls, v1 - ls);
    }
}

// ---------------- launcher ---------------------------------------------------
extern "C" void kernel_launch(void* const* d_in, const int* in_sizes, int n_in,
                              void* d_out, int out_size) {
    const float* x      = (const float*)d_in[0];
    const int*   ei     = (const int*)  d_in[1];
    const float* W1     = (const float*)d_in[2];
    const float* a_src1 = (const float*)d_in[3];
    const float* a_dst1 = (const float*)d_in[4];
    const float* b1     = (const float*)d_in[5];
    const float* W2     = (const float*)d_in[6];
    const float* a_src2 = (const float*)d_in[7];
    const float* a_dst2 = (const float*)d_in[8];
    const float* b2     = (const float*)d_in[9];
    float* out = (float*)d_out;

    int n = in_sizes[0] / 128;
    int e = in_sizes[1] / 2;
    int T = e + n;
    int nb = (n + 1023) >> 10;

    // Fork a second stream for the CSR build (independent of gemm1 chain).
    // Stream/events intentionally NOT destroyed (capture safety; bounded leak).
    cudaStream_t s2;
    cudaStreamCreateWithFlags(&s2, cudaStreamNonBlocking);
    cudaEvent_t evFork, evJoin;
    cudaEventCreateWithFlags(&evFork, cudaEventDisableTiming);
    cudaEventCreateWithFlags(&evJoin, cudaEventDisableTiming);

    cudaEventRecord(evFork, 0);
    cudaStreamWaitEvent(s2, evFork, 0);

    k_zero_deg <<<(n + 255) / 256, 256, 0, s2>>>(n);
    k_hist     <<<(T + 255) / 256, 256, 0, s2>>>(ei, e, n);
    k_blocksum <<<nb, 256, 0, s2>>>();
    k_scanb    <<<1, 1024, 0, s2>>>(nb, n);
    k_writerow <<<nb, 256, 0, s2>>>();
    k_scatter  <<<(T + 255) / 256, 256, 0, s2>>>(ei, e, n);
    cudaEventRecord(evJoin, s2);

    k_gemm1    <<<(n + G1_TM - 1) / G1_TM, 256>>>(x, W1, a_src1, a_dst1, n);

    cudaStreamWaitEvent(0, evJoin, 0);
    k_agg1f    <<<1184, 256>>>(b1, W2, a_src2, a_dst2, n);
    k_agg2f    <<<1184, 256>>>(b2, out, n);
}

// round 11
// speedup vs baseline: 1.0391x; 1.0078x over previous
#include <cuda_runtime.h>
#include <cuda_fp16.h>
#include <math.h>

#define MAXN 100000
#define MAXE 1600000
#define MAXT (MAXN + MAXE)
#define NB_MAX 1024

// ---------------- static device scratch -------------------------------------
__device__ __align__(16) __half g_h1h[MAXN * 64];   // layer1 features, fp16
__device__ __align__(16) float g_as1 [MAXN * 4];
__device__ __align__(16) float g_ad1 [MAXN * 4];
__device__ __align__(16) __half g_h2h[MAXN * 40];   // layer2 features, fp16
__device__            float g_as2 [MAXN];
__device__            float g_ad2 [MAXN];
// CSR structures (rebuilt every launch; dst-sorted). Padded so int4/scan code
// never needs bounds checks.
__device__ int g_deg     [MAXN + 1024];
__device__ int g_rowstart[MAXN + 1024];
__device__ int g_cursor  [MAXN + 1024];
__device__ int g_srcs    [MAXT];
__device__ int g_bsum[NB_MAX];
__device__ int g_boff[NB_MAX];

__device__ __forceinline__ float lrelu(float v) { return v > 0.f ? v : 0.2f * v; }

// ---------------- CSR build --------------------------------------------------
__global__ void k_zero_deg(int n) {
    int i = blockIdx.x * blockDim.x + threadIdx.x;
    if (i < n) g_deg[i] = 0;
}

__global__ void k_hist(const int* __restrict__ ei, int e, int n) {
    int t = blockIdx.x * blockDim.x + threadIdx.x;
    if (t >= e + n) return;
    int dst = (t < e) ? __ldg(&ei[e + t]) : (t - e);
    atomicAdd(&g_deg[dst], 1);
}

__global__ void k_blocksum() {
    __shared__ int wsum[8];
    int b = blockIdx.x, tid = threadIdx.x;
    int4 d = *(const int4*)&g_deg[b * 1024 + tid * 4];
    int s = d.x + d.y + d.z + d.w;
    #pragma unroll
    for (int off = 16; off; off >>= 1) s += __shfl_down_sync(0xffffffffu, s, off);
    if ((tid & 31) == 0) wsum[tid >> 5] = s;
    __syncthreads();
    if (tid == 0) {
        int t = 0;
        #pragma unroll
        for (int i = 0; i < 8; i++) t += wsum[i];
        g_bsum[b] = t;
    }
}

__global__ void k_scanb(int nb, int n) {
    __shared__ int sm[1024];
    int tid = threadIdx.x;
    int v = (tid < nb) ? g_bsum[tid] : 0;
    sm[tid] = v;
    __syncthreads();
    for (int off = 1; off < 1024; off <<= 1) {
        int a = (tid >= off) ? sm[tid - off] : 0;
        __syncthreads();
        sm[tid] += a;
        __syncthreads();
    }
    if (tid < nb) g_boff[tid] = sm[tid] - v;
    if (tid == 1023) g_rowstart[n] = sm[1023];
}

__global__ void k_writerow() {
    __shared__ int tsum[256];
    int b = blockIdx.x, tid = threadIdx.x;
    int idx = b * 1024 + tid * 4;
    int4 d = *(const int4*)&g_deg[idx];
    int s = d.x + d.y + d.z + d.w;
    tsum[tid] = s;
    __syncthreads();
    for (int off = 1; off < 256; off <<= 1) {
        int a = (tid >= off) ? tsum[tid - off] : 0;
        __syncthreads();
        tsum[tid] += a;
        __syncthreads();
    }
    int r = tsum[tid] - s + g_boff[b];
    g_rowstart[idx] = r;     g_cursor[idx] = r;     r += d.x;
    g_rowstart[idx + 1] = r; g_cursor[idx + 1] = r; r += d.y;
    g_rowstart[idx + 2] = r; g_cursor[idx + 2] = r; r += d.z;
    g_rowstart[idx + 3] = r; g_cursor[idx + 3] = r;
}

__global__ void k_scatter(const int* __restrict__ ei, int e, int n) {
    int t = blockIdx.x * blockDim.x + threadIdx.x;
    if (t >= e + n) return;
    int src, dst;
    if (t < e) { src = __ldg(&ei[t]); dst = __ldg(&ei[e + t]); } else { src = dst = t - e; }
    int pos = atomicAdd(&g_cursor[dst], 1);
    g_srcs[pos] = src;
}

// ------- tiled GEMM1 + fused alpha1; h1 stored as fp16 ----------------------
#define G1_TM 64
__global__ void k_gemm1(const float* __restrict__ x, const float* __restrict__ W1,
                        const float* __restrict__ a_s, const float* __restrict__ a_d,
                        int n) {
    __shared__ float As[G1_TM * 68];
    __shared__ float Bs[64 * 64];
    int tid = threadIdx.x;
    int row0 = blockIdx.x * G1_TM;
    int tr = tid >> 4, tc = tid & 15;

    float acc[4][4] = {};
    const float4* Bs4 = (const float4*)Bs;

    #pragma unroll
    for (int kt = 0; kt < 2; kt++) {
        for (int i = tid; i < 64 * 64; i += 256) {
            int c = i >> 6, kk = i & 63;
            Bs[kk * 64 + c] = W1[c * 128 + kt * 64 + kk];
        }
        for (int i = tid; i < G1_TM * 16; i += 256) {
            int r = i >> 4, k4 = i & 15;
            int row = row0 + r;
            float4 v = (row < n) ? *(const float4*)&x[(size_t)row * 128 + kt * 64 + k4 * 4]
                                 : make_float4(0.f, 0.f, 0.f, 0.f);
            *(float4*)&As[r * 68 + k4 * 4] = v;
        }
        __syncthreads();

        #pragma unroll 4
        for (int k = 0; k < 64; k++) {
            float a0 = As[(tr * 4 + 0) * 68 + k];
            float a1 = As[(tr * 4 + 1) * 68 + k];
            float a2 = As[(tr * 4 + 2) * 68 + k];
            float a3 = As[(tr * 4 + 3) * 68 + k];
            float4 b = Bs4[k * 16 + tc];
            acc[0][0] = fmaf(a0, b.x, acc[0][0]); acc[0][1] = fmaf(a0, b.y, acc[0][1]);
            acc[0][2] = fmaf(a0, b.z, acc[0][2]); acc[0][3] = fmaf(a0, b.w, acc[0][3]);
            acc[1][0] = fmaf(a1, b.x, acc[1][0]); acc[1][1] = fmaf(a1, b.y, acc[1][1]);
            acc[1][2] = fmaf(a1, b.z, acc[1][2]); acc[1][3] = fmaf(a1, b.w, acc[1][3]);
            acc[2][0] = fmaf(a2, b.x, acc[2][0]); acc[2][1] = fmaf(a2, b.y, acc[2][1]);
            acc[2][2] = fmaf(a2, b.z, acc[2][2]); acc[2][3] = fmaf(a2, b.w, acc[2][3]);
            acc[3][0] = fmaf(a3, b.x, acc[3][0]); acc[3][1] = fmaf(a3, b.y, acc[3][1]);
            acc[3][2] = fmaf(a3, b.z, acc[3][2]); acc[3][3] = fmaf(a3, b.w, acc[3][3]);
        }
        __syncthreads();
    }

    int col = tc * 4;
    #pragma unroll
    for (int i = 0; i < 4; i++) {
        int row = row0 + tr * 4 + i;
        if (row < n) {
            __half2 p0 = __floats2half2_rn(acc[i][0], acc[i][1]);
            __half2 p1 = __floats2half2_rn(acc[i][2], acc[i][3]);
            *(__half2*)&g_h1h[(size_t)row * 64 + col]     = p0;
            *(__half2*)&g_h1h[(size_t)row * 64 + col + 2] = p1;
        }
    }

    float as0 = a_s[col], as1v = a_s[col + 1], as2v = a_s[col + 2], as3 = a_s[col + 3];
    float ad0 = a_d[col], ad1v = a_d[col + 1], ad2v = a_d[col + 2], ad3 = a_d[col + 3];
    float ps[4], pd[4];
    #pragma unroll
    for (int i = 0; i < 4; i++) {
        ps[i] = acc[i][0] * as0 + acc[i][1] * as1v + acc[i][2] * as2v + acc[i][3] * as3;
        pd[i] = acc[i][0] * ad0 + acc[i][1] * ad1v + acc[i][2] * ad2v + acc[i][3] * ad3;
    }
    #pragma unroll
    for (int off = 1; off <= 2; off <<= 1) {
        #pragma unroll
        for (int i = 0; i < 4; i++) {
            ps[i] += __shfl_xor_sync(0xffffffffu, ps[i], off);
            pd[i] += __shfl_xor_sync(0xffffffffu, pd[i], off);
        }
    }
    if ((tc & 3) == 0) {
        int head = tc >> 2;
        #pragma unroll
        for (int i = 0; i < 4; i++) {
            int row = row0 + tr * 4 + i;
            if (row < n) {
                g_as1[row * 4 + head] = ps[i];
                g_ad1[row * 4 + head] = pd[i];
            }
        }
    }
}

// ------ layer1 fused: softmax-aggregate + relu+bias + gemm2 + alpha2 ---------
// R7 structure (one edge per inner iteration), fp16 h1 gather (half traffic).
__global__ void k_agg1f(const float* __restrict__ b1, const float* __restrict__ W2,
                        const float* __restrict__ a_s2, const float* __restrict__ a_d2,
                        int n) {
    __shared__ float Wt[64 * 40];
    __shared__ float sa[40], sd[40], b1s[64];
    __shared__ __align__(16) float es[8][128];
    __shared__ int ss[8][32];
    int tid = threadIdx.x;
    for (int i = tid; i < 40 * 64; i += 256) {
        int c = i / 64, k = i - c * 64;
        Wt[k * 40 + c] = W2[i];
    }
    if (tid < 40) { sa[tid] = a_s2[tid]; sd[tid] = a_d2[tid]; }
    if (tid < 64) b1s[tid] = b1[tid];
    __syncthreads();

    int w = tid >> 5, lane = tid & 31;
    int head = lane >> 3;
    int ngroups = gridDim.x * 8;

    for (int dst = blockIdx.x * 8 + w; dst < n; dst += ngroups) {
        int row = g_rowstart[dst], end = g_rowstart[dst + 1];
        float4 ad = *(const float4*)&g_ad1[dst * 4];
        float2 acc = make_float2(0.f, 0.f);
        float4 den = make_float4(0.f, 0.f, 0.f, 0.f);

        for (int base = row; base < end; base += 32) {
            int k = base + lane;
            float4 e4 = make_float4(0.f, 0.f, 0.f, 0.f);
            int s = 0;
            if (k < end) {
                s = g_srcs[k];
                float4 as = *(const float4*)&g_as1[s * 4];
                e4.x = __expf(lrelu(as.x + ad.x));
                e4.y = __expf(lrelu(as.y + ad.y));
                e4.z = __expf(lrelu(as.z + ad.z));
                e4.w = __expf(lrelu(as.w + ad.w));
                den.x += e4.x; den.y += e4.y; den.z += e4.z; den.w += e4.w;
            }
            ss[w][lane] = s;
            *(float4*)&es[w][lane * 4] = e4;
            __syncwarp();
            int m = min(32, end - base);
            #pragma unroll 4
            for (int k2 = 0; k2 < m; k2++) {
                int s2   = ss[w][k2];
                float ek = es[w][k2 * 4 + head];
                float2 h = __half22float2(*(const __half2*)&g_h1h[(size_t)s2 * 64 + lane * 2]);
                acc.x = fmaf(ek, h.x, acc.x);
                acc.y = fmaf(ek, h.y, acc.y);
            }
            __syncwarp();
        }
        #pragma unroll
        for (int off = 16; off; off >>= 1) {
            den.x += __shfl_xor_sync(0xffffffffu, den.x, off);
            den.y += __shfl_xor_sync(0xffffffffu, den.y, off);
            den.z += __shfl_xor_sync(0xffffffffu, den.z, off);
            den.w += __shfl_xor_sync(0xffffffffu, den.w, off);
        }
        float d   = head == 0 ? den.x : head == 1 ? den.y : head == 2 ? den.z : den.w;
        float inv = __frcp_rn(d);
        float vx = fmaxf(acc.x * inv + b1s[2 * lane],     0.f);
        float vy = fmaxf(acc.y * inv + b1s[2 * lane + 1], 0.f);
        float o0 = 0.f, o1 = 0.f;
        #pragma unroll
        for (int k = 0; k < 64; k++) {
            float xk = __shfl_sync(0xffffffffu, (k & 1) ? vy : vx, k >> 1);
            o0 = fmaf(Wt[k * 40 + lane], xk, o0);
            if (lane < 8) o1 = fmaf(Wt[k * 40 + 32 + lane], xk, o1);
        }
        g_h2h[(size_t)dst * 40 + lane] = __float2half_rn(o0);
        if (lane < 8) g_h2h[(size_t)dst * 40 + 32 + lane] = __float2half_rn(o1);
        float ps = o0 * sa[lane] + (lane < 8 ? o1 * sa[32 + lane] : 0.f);
        float pd = o0 * sd[lane] + (lane < 8 ? o1 * sd[32 + lane] : 0.f);
        #pragma unroll
        for (int off = 16; off; off >>= 1) {
            ps += __shfl_xor_sync(0xffffffffu, ps, off);
            pd += __shfl_xor_sync(0xffffffffu, pd, off);
        }
        if (lane == 0) { g_as2[dst] = ps; g_ad2[dst] = pd; }
    }
}

// ------ layer2 fused: softmax-aggregate + bias + log_softmax -> out ----------
// Lane li<20 owns channel pair (2li, 2li+1) via half2 gathers.
__global__ void k_agg2f(const float* __restrict__ b2, float* __restrict__ out, int n) {
    __shared__ float es[8][32];
    __shared__ int   ss[8][32];
    int tid = threadIdx.x;
    int w = tid >> 5, lane = tid & 31;
    bool act = lane < 20;
    int ngroups = gridDim.x * 8;

    float b2x = act ? __ldg(&b2[2 * lane])     : 0.f;
    float b2y = act ? __ldg(&b2[2 * lane + 1]) : 0.f;

    for (int dst = blockIdx.x * 8 + w; dst < n; dst += ngroups) {
        int row = g_rowstart[dst], end = g_rowstart[dst + 1];
        float ad = g_ad2[dst];
        float2 acc = make_float2(0.f, 0.f);
        float den = 0.f;

        for (int base = row; base < end; base += 32) {
            int k = base + lane;
            float e = 0.f;
            int s = 0;
            if (k < end) {
                s = g_srcs[k];
                e = __expf(lrelu(g_as2[s] + ad));
                den += e;
            }
            ss[w][lane] = s;
            es[w][lane] = e;
            __syncwarp();
            int m = min(32, end - base);
            #pragma unroll 4
            for (int k2 = 0; k2 < m; k2++) {
                int s2   = ss[w][k2];
                float ek = es[w][k2];
                if (act) {
                    float2 h = __half22float2(*(const __half2*)&g_h2h[(size_t)s2 * 40 + lane * 2]);
                    acc.x = fmaf(ek, h.x, acc.x);
                    acc.y = fmaf(ek, h.y, acc.y);
                }
            }
            __syncwarp();
        }
        #pragma unroll
        for (int off = 16; off; off >>= 1) den += __shfl_xor_sync(0xffffffffu, den, off);
        float inv = __frcp_rn(den);
        float v0 = fmaf(acc.x, inv, b2x);
        float v1 = fmaf(acc.y, inv, b2y);
        float mx = act ? fmaxf(v0, v1) : -1e30f;
        #pragma unroll
        for (int off = 16; off; off >>= 1) mx = fmaxf(mx, __shfl_xor_sync(0xffffffffu, mx, off));
        float se = act ? (__expf(v0 - mx) + __expf(v1 - mx)) : 0.f;
        #pragma unroll
        for (int off = 16; off; off >>= 1) se += __shfl_xor_sync(0xffffffffu, se, off);
        float ls = mx + logf(se);
        if (act)
            *(float2*)&out[(size_t)dst * 40 + lane * 2] = make_float2(v0 - ls, v1 - ls);
    }
}

// ---------------- launcher ---------------------------------------------------
extern "C" void kernel_launch(void* const* d_in, const int* in_sizes, int n_in,
                              void* d_out, int out_size) {
    const float* x      = (const float*)d_in[0];
    const int*   ei     = (const int*)  d_in[1];
    const float* W1     = (const float*)d_in[2];
    const float* a_src1 = (const float*)d_in[3];
    const float* a_dst1 = (const float*)d_in[4];
    const float* b1     = (const float*)d_in[5];
    const float* W2     = (const float*)d_in[6];
    const float* a_src2 = (const float*)d_in[7];
    const float* a_dst2 = (const float*)d_in[8];
    const float* b2     = (const float*)d_in[9];
    float* out = (float*)d_out;

    int n = in_sizes[0] / 128;
    int e = in_sizes[1] / 2;
    int T = e + n;
    int nb = (n + 1023) >> 10;

    // Fork a second stream for the CSR build (independent of gemm1 chain).
    // Stream/events intentionally NOT destroyed (capture safety; bounded leak).
    cudaStream_t s2;
    cudaStreamCreateWithFlags(&s2, cudaStreamNonBlocking);
    cudaEvent_t evFork, evJoin;
    cudaEventCreateWithFlags(&evFork, cudaEventDisableTiming);
    cudaEventCreateWithFlags(&evJoin, cudaEventDisableTiming);

    cudaEventRecord(evFork, 0);
    cudaStreamWaitEvent(s2, evFork, 0);

    k_zero_deg <<<(n + 255) / 256, 256, 0, s2>>>(n);
    k_hist     <<<(T + 255) / 256, 256, 0, s2>>>(ei, e, n);
    k_blocksum <<<nb, 256, 0, s2>>>();
    k_scanb    <<<1, 1024, 0, s2>>>(nb, n);
    k_writerow <<<nb, 256, 0, s2>>>();
    k_scatter  <<<(T + 255) / 256, 256, 0, s2>>>(ei, e, n);
    cudaEventRecord(evJoin, s2);

    k_gemm1    <<<(n + G1_TM - 1) / G1_TM, 256>>>(x, W1, a_src1, a_dst1, n);

    cudaStreamWaitEvent(0, evJoin, 0);
    k_agg1f    <<<1184, 256>>>(b1, W2, a_src2, a_dst2, n);
    k_agg2f    <<<1184, 256>>>(b2, out, n);
}